// round 10
// baseline (speedup 1.0000x reference)
#include <cuda_runtime.h>
#include <cstddef>

#define NN 50000
#define NE_MAX 800000
#define FIN 128
#define H1 100
#define H2 200
#define FOUT 16
#define C4_H1 (H1 / 4)   // 25 float4 chunks per row

// -------- scratch (static device globals; no allocation) --------
__device__ __align__(16) int   g_deg[NN];
__device__ __align__(16) float g_dis[NN];
__device__ __align__(16) int   g_off[NN];
__device__ __align__(16) int   g_cur[NN];
__device__               int   g_total;
__device__ __align__(16) int   g_src[NE_MAX];
__device__ __align__(16) float g_y1 [(size_t)NN * H1];
__device__ __align__(16) float g_y2 [(size_t)NN * H1];
__device__ __align__(16) float g_s2 [(size_t)NN * H1];
__device__ __align__(16) float g_xw2[(size_t)NN * H2];
// transposed, zero-padded weights: Wt[j][k], j padded to NJ*32 rows
__device__ __align__(16) float g_wt1[128 * FIN];   // W1^T: 128 rows (pad of 100) x 128
__device__ __align__(16) float g_wt2[224 * H1];    // W2^T: 224 rows (pad of 200) x 100

// ================= weight transpose (Wt[j][k] = W[k][j], zero-padded) =================
__global__ void k_transpose(const float* __restrict__ W, float* __restrict__ Wt,
                            int K, int N, int Npad) {
    int idx = blockIdx.x * blockDim.x + threadIdx.x;
    if (idx >= Npad * K) return;
    int j = idx / K;
    int k = idx - j * K;
    Wt[idx] = (j < N) ? W[(size_t)k * N + j] : 0.f;
}

// ================= degree / CSR build =================
__global__ void k_count_deg(const int* __restrict__ col, int nE) {
    int q = blockIdx.x * blockDim.x + threadIdx.x;
    int nQ = nE >> 2;
    if (q < nQ) {
        int4 c = *(const int4*)(col + q * 4);
        if ((unsigned)c.x < (unsigned)NN) atomicAdd(&g_deg[c.x], 1);
        if ((unsigned)c.y < (unsigned)NN) atomicAdd(&g_deg[c.y], 1);
        if ((unsigned)c.z < (unsigned)NN) atomicAdd(&g_deg[c.z], 1);
        if ((unsigned)c.w < (unsigned)NN) atomicAdd(&g_deg[c.w], 1);
    } else if (q == nQ) {
        for (int e = nQ * 4; e < nE; e++) {
            int t = col[e];
            if ((unsigned)t < (unsigned)NN) atomicAdd(&g_deg[t], 1);
        }
    }
}

__global__ void k_assign(int n) {
    int i = blockIdx.x * blockDim.x + threadIdx.x;
    if (i >= n) return;
    int d = g_deg[i];
    g_dis[i] = rsqrtf((float)(d + 1));
    int off = atomicAdd(&g_total, d);
    g_off[i] = off;
    g_cur[i] = off;
}

__global__ void k_fill(const int* __restrict__ row, const int* __restrict__ col, int nE) {
    int q = blockIdx.x * blockDim.x + threadIdx.x;
    int nQ = nE >> 2;
    if (q < nQ) {
        int4 r = *(const int4*)(row + q * 4);
        int4 c = *(const int4*)(col + q * 4);
        int s0 = -1, s1 = -1, s2 = -1, s3 = -1;
        if ((unsigned)c.x < (unsigned)NN && (unsigned)r.x < (unsigned)NN) s0 = atomicAdd(&g_cur[c.x], 1);
        if ((unsigned)c.y < (unsigned)NN && (unsigned)r.y < (unsigned)NN) s1 = atomicAdd(&g_cur[c.y], 1);
        if ((unsigned)c.z < (unsigned)NN && (unsigned)r.z < (unsigned)NN) s2 = atomicAdd(&g_cur[c.z], 1);
        if ((unsigned)c.w < (unsigned)NN && (unsigned)r.w < (unsigned)NN) s3 = atomicAdd(&g_cur[c.w], 1);
        if (s0 >= 0) g_src[s0] = r.x;
        if (s1 >= 0) g_src[s1] = r.y;
        if (s2 >= 0) g_src[s2] = r.z;
        if (s3 >= 0) g_src[s3] = r.w;
    } else if (q == nQ) {
        for (int e = nQ * 4; e < nE; e++) {
            int rr = row[e], t = col[e];
            if ((unsigned)rr >= (unsigned)NN || (unsigned)t >= (unsigned)NN) continue;
            int slot = atomicAdd(&g_cur[t], 1);
            g_src[slot] = rr;
        }
    }
}

// ================= warp-aligned dense with TRANSPOSED weights =================
// Wt is [NJ*32][K] (zero-padded rows). Lane j loads Wt[j][k0..k0+3] as one LDG.128.
// IN_MODE: 0=plain, 1=relu.  OUT_SCALE: multiply by dis[row].
template <int K, int N, int NJ, int RPW, int WARPS, int IN_MODE, int OUT_SCALE>
__global__ void __launch_bounds__(WARPS * 32)
k_dense_t(const float* __restrict__ in, const float* __restrict__ Wt,
          const float* __restrict__ bias, float* __restrict__ out, int nRows) {
    constexpr int ROWS = WARPS * RPW;
    constexpr int KV = K / 4;
    __shared__ __align__(16) float s_in[ROWS][K];

    int r0  = blockIdx.x * ROWS;
    int tid = threadIdx.y * 32 + threadIdx.x;
    constexpr int NTH = WARPS * 32;

    const float4* in4 = (const float4*)in;
    for (int i = tid; i < ROWS * KV; i += NTH) {
        int r = i / KV;
        int c = i - r * KV;
        int gr = r0 + r;
        float4 v = make_float4(0.f, 0.f, 0.f, 0.f);
        if (gr < nRows) {
            v = in4[(size_t)gr * KV + c];
            if (IN_MODE == 1) {
                v.x = fmaxf(v.x, 0.f); v.y = fmaxf(v.y, 0.f);
                v.z = fmaxf(v.z, 0.f); v.w = fmaxf(v.w, 0.f);
            }
        }
        *(float4*)&s_in[r][c * 4] = v;
    }
    __syncthreads();

    int lane  = threadIdx.x;
    int rbase = threadIdx.y * RPW;

    float acc[RPW][NJ];
#pragma unroll
    for (int r = 0; r < RPW; r++)
#pragma unroll
        for (int jj = 0; jj < NJ; jj++) acc[r][jj] = 0.f;

#pragma unroll 2
    for (int k0 = 0; k0 < K; k0 += 4) {
        float4 wv[NJ];
#pragma unroll
        for (int jj = 0; jj < NJ; jj++)
            wv[jj] = __ldg((const float4*)&Wt[(size_t)(lane + jj * 32) * K + k0]);
#pragma unroll
        for (int r = 0; r < RPW; r++) {
            float4 a = *(const float4*)&s_in[rbase + r][k0];  // warp broadcast
#pragma unroll
            for (int jj = 0; jj < NJ; jj++)
                acc[r][jj] = fmaf(a.x, wv[jj].x, fmaf(a.y, wv[jj].y,
                             fmaf(a.z, wv[jj].z, fmaf(a.w, wv[jj].w, acc[r][jj]))));
        }
    }

    float bv[NJ];
#pragma unroll
    for (int jj = 0; jj < NJ; jj++) {
        int j = lane + jj * 32;
        bv[jj] = (bias != nullptr && j < N) ? __ldg(&bias[j]) : 0.f;
    }
#pragma unroll
    for (int r = 0; r < RPW; r++) {
        int gr = r0 + rbase + r;
        if (gr < nRows) {
            float d = OUT_SCALE ? g_dis[gr] : 1.f;
#pragma unroll
            for (int jj = 0; jj < NJ; jj++) {
                int j = lane + jj * 32;
                if (j < N) out[(size_t)gr * N + j] = (acc[r][jj] + bv[jj]) * d;
            }
        }
    }
}

// ======== old-style dense (FC: N=16 divides warps cleanly) ========
template <int K, int N, int G, int RPB, int IN_MODE>
__global__ void k_dense(const float* __restrict__ in, const float* __restrict__ W,
                        const float* __restrict__ bias, float* __restrict__ out,
                        int nRows) {
    constexpr int ROWS = G * RPB;
    __shared__ __align__(16) float s_in[ROWS][K];

    int r0  = blockIdx.x * ROWS;
    int tid = threadIdx.y * N + threadIdx.x;
    int nth = N * G;

    for (int i = tid; i < ROWS * K; i += nth) {
        int r = i / K;
        int k = i - r * K;
        int gr = r0 + r;
        float v = 0.f;
        if (gr < nRows) {
            v = in[(size_t)gr * K + k];
            if (IN_MODE == 1) v = fmaxf(v, 0.f);
        }
        s_in[r][k] = v;
    }
    __syncthreads();

    int j     = threadIdx.x;
    int rbase = threadIdx.y * RPB;

    float acc[RPB];
#pragma unroll
    for (int r = 0; r < RPB; r++) acc[r] = 0.f;

#pragma unroll 4
    for (int k0 = 0; k0 < K; k0 += 4) {
        float w0 = __ldg(&W[(size_t)(k0 + 0) * N + j]);
        float w1 = __ldg(&W[(size_t)(k0 + 1) * N + j]);
        float w2 = __ldg(&W[(size_t)(k0 + 2) * N + j]);
        float w3 = __ldg(&W[(size_t)(k0 + 3) * N + j]);
#pragma unroll
        for (int r = 0; r < RPB; r++) {
            float4 a = *(const float4*)&s_in[rbase + r][k0];
            acc[r] = fmaf(a.x, w0, fmaf(a.y, w1, fmaf(a.z, w2, fmaf(a.w, w3, acc[r]))));
        }
    }

    float b = (bias != nullptr) ? __ldg(&bias[j]) : 0.f;
#pragma unroll
    for (int r = 0; r < RPB; r++) {
        int gr = r0 + rbase + r;
        if (gr < nRows) out[(size_t)gr * N + j] = acc[r] + b;
    }
}

// ================= CSR gather aggregation (warp per node) =================
template <int C4, int MODE>
__global__ void __launch_bounds__(256)
k_gather(const float4* __restrict__ y, const float* __restrict__ bias,
         float4* __restrict__ out, int nN) {
    int node = blockIdx.x * blockDim.y + threadIdx.y;
    if (node >= nN) return;
    int lane  = threadIdx.x;
    int start = g_off[node];
    int cnt   = g_deg[node];
    bool act  = (lane < C4);

    float4 acc = make_float4(0.f, 0.f, 0.f, 0.f);
    if (act) acc = y[(size_t)node * C4 + lane];

    int j = 0;
    for (; j + 8 <= cnt; j += 8) {
        int rr[8];
#pragma unroll
        for (int u = 0; u < 8; u++) rr[u] = __ldg(&g_src[start + j + u]);
#pragma unroll
        for (int u = 0; u < 8; u++) {
            if (act) {
                float4 v = __ldg(&y[(size_t)rr[u] * C4 + lane]);
                acc.x += v.x; acc.y += v.y; acc.z += v.z; acc.w += v.w;
            }
        }
    }
    if (j + 4 <= cnt) {
        int rr[4];
#pragma unroll
        for (int u = 0; u < 4; u++) rr[u] = __ldg(&g_src[start + j + u]);
#pragma unroll
        for (int u = 0; u < 4; u++) {
            if (act) {
                float4 v = __ldg(&y[(size_t)rr[u] * C4 + lane]);
                acc.x += v.x; acc.y += v.y; acc.z += v.z; acc.w += v.w;
            }
        }
        j += 4;
    }
    for (; j < cnt; j++) {
        int r = __ldg(&g_src[start + j]);
        if (act) {
            float4 v = __ldg(&y[(size_t)r * C4 + lane]);
            acc.x += v.x; acc.y += v.y; acc.z += v.z; acc.w += v.w;
        }
    }

    if (act) {
        float d = g_dis[node];
        float4 o;
        if (MODE == 1) {
            float4 b = *(const float4*)&bias[lane * 4];
            o.x = d * fmaxf(fmaf(d, acc.x, b.x), 0.f);
            o.y = d * fmaxf(fmaf(d, acc.y, b.y), 0.f);
            o.z = d * fmaxf(fmaf(d, acc.z, b.z), 0.f);
            o.w = d * fmaxf(fmaf(d, acc.w, b.w), 0.f);
        } else {
            o.x = d * acc.x; o.y = d * acc.y; o.z = d * acc.z; o.w = d * acc.w;
        }
        out[(size_t)node * C4 + lane] = o;
    }
}

// ================= launch =================
extern "C" void kernel_launch(void* const* d_in, const int* in_sizes, int n_in,
                              void* d_out, int out_size) {
    const float* x   = (const float*)d_in[0];
    const int*   ei  = (const int*)d_in[1];
    const float* W1  = (const float*)d_in[2];
    const float* b1  = (const float*)d_in[3];
    const float* W2  = (const float*)d_in[4];
    const float* b2  = (const float*)d_in[5];
    const float* Wfc = (const float*)d_in[6];
    const float* bfc = (const float*)d_in[7];
    float*       out = (float*)d_out;

    int nN = in_sizes[0] / FIN;
    int nE = in_sizes[1] / 2;
    const int* rowI = ei;
    const int* colI = ei + nE;

    float *p_y1, *p_y2, *p_s2, *p_xw2, *p_wt1, *p_wt2;
    int   *p_deg, *p_total;
    cudaGetSymbolAddress((void**)&p_y1,   g_y1);
    cudaGetSymbolAddress((void**)&p_y2,   g_y2);
    cudaGetSymbolAddress((void**)&p_s2,   g_s2);
    cudaGetSymbolAddress((void**)&p_xw2,  g_xw2);
    cudaGetSymbolAddress((void**)&p_wt1,  g_wt1);
    cudaGetSymbolAddress((void**)&p_wt2,  g_wt2);
    cudaGetSymbolAddress((void**)&p_deg,  g_deg);
    cudaGetSymbolAddress((void**)&p_total, g_total);

    // --- degree + CSR build ---
    cudaMemsetAsync(p_deg, 0, (size_t)nN * sizeof(int));
    cudaMemsetAsync(p_total, 0, sizeof(int));
    {
        int nQ = nE / 4 + 1;
        k_count_deg<<<(nQ + 255) / 256, 256>>>(colI, nE);
        k_assign   <<<(nN + 255) / 256, 256>>>(nN);
        k_fill     <<<(nQ + 255) / 256, 256>>>(rowI, colI, nE);
    }

    // --- weight transposes (tiny) ---
    k_transpose<<<(128 * FIN + 255) / 256, 256>>>(W1, p_wt1, FIN, H1, 128);
    k_transpose<<<(224 * H1 + 255) / 256, 256>>>(W2, p_wt2, H1, H2, 224);

    // --- layer 1: y1 = d_r ⊙ (x @ W1) ---
    k_dense_t<FIN, H1, 4, 8, 8, 0, 1><<<(nN + 63) / 64, dim3(32, 8)>>>(
        x, p_wt1, nullptr, p_y1, nN);

    // --- agg1 + mid fused: y2 = d ⊙ relu(d ⊙ (y1_self + Σ y1[src]) + b1) ---
    k_gather<C4_H1, 1><<<(nN + 7) / 8, dim3(32, 8)>>>(
        (const float4*)p_y1, b1, (float4*)p_y2, nN);

    // --- agg2 (commuted before GEMM): s2 = d ⊙ (y2_self + Σ y2[src]) ---
    k_gather<C4_H1, 2><<<(nN + 7) / 8, dim3(32, 8)>>>(
        (const float4*)p_y2, nullptr, (float4*)p_s2, nN);

    // --- layer 2 GEMM: xw2 = s2 @ W2 + b2 ---
    k_dense_t<H1, H2, 7, 8, 8, 0, 0><<<(nN + 63) / 64, dim3(32, 8)>>>(
        p_s2, p_wt2, b2, p_xw2, nN);

    // --- FC: out = relu(xw2) @ Wfc + bfc ---
    k_dense<H2, FOUT, 8, 4, 1><<<(nN + 31) / 32, dim3(FOUT, 8)>>>(
        p_xw2, Wfc, bfc, out, nN);
}

// round 11
// speedup vs baseline: 2.0812x; 2.0812x over previous
#include <cuda_runtime.h>
#include <cuda_fp16.h>
#include <cstddef>

#define NN 50000
#define NE_MAX 800000
#define FIN 128
#define H1 100
#define H2 200
#define FOUT 16
#define C4_H1 (H1 / 4)   // 25 4-float chunks per row

// -------- scratch (static device globals; no allocation) --------
__device__ __align__(16) int    g_deg[NN];
__device__ __align__(16) float  g_dis[NN];
__device__ __align__(16) int    g_off[NN];
__device__ __align__(16) int    g_cur[NN];
__device__               int    g_total;
__device__ __align__(16) int    g_src[NE_MAX];
__device__ __align__(16) __half g_y1h[(size_t)NN * H1];  // fp16 gather payload 1
__device__ __align__(16) __half g_y2h[(size_t)NN * H1];  // fp16 gather payload 2
__device__ __align__(16) float  g_s2 [(size_t)NN * H1];  // fp32 dense2 input
__device__ __align__(16) float  g_xw2[(size_t)NN * H2];

// ================= degree / CSR build =================
__global__ void k_count_deg(const int* __restrict__ col, int nE) {
    int q = blockIdx.x * blockDim.x + threadIdx.x;
    int nQ = nE >> 2;
    if (q < nQ) {
        int4 c = *(const int4*)(col + q * 4);
        if ((unsigned)c.x < (unsigned)NN) atomicAdd(&g_deg[c.x], 1);
        if ((unsigned)c.y < (unsigned)NN) atomicAdd(&g_deg[c.y], 1);
        if ((unsigned)c.z < (unsigned)NN) atomicAdd(&g_deg[c.z], 1);
        if ((unsigned)c.w < (unsigned)NN) atomicAdd(&g_deg[c.w], 1);
    } else if (q == nQ) {
        for (int e = nQ * 4; e < nE; e++) {
            int t = col[e];
            if ((unsigned)t < (unsigned)NN) atomicAdd(&g_deg[t], 1);
        }
    }
}

__global__ void k_assign(int n) {
    int i = blockIdx.x * blockDim.x + threadIdx.x;
    if (i >= n) return;
    int d = g_deg[i];
    g_dis[i] = rsqrtf((float)(d + 1));
    int off = atomicAdd(&g_total, d);
    g_off[i] = off;
    g_cur[i] = off;
}

__global__ void k_fill(const int* __restrict__ row, const int* __restrict__ col, int nE) {
    int q = blockIdx.x * blockDim.x + threadIdx.x;
    int nQ = nE >> 2;
    if (q < nQ) {
        int4 r = *(const int4*)(row + q * 4);
        int4 c = *(const int4*)(col + q * 4);
        int s0 = -1, s1 = -1, s2 = -1, s3 = -1;
        if ((unsigned)c.x < (unsigned)NN && (unsigned)r.x < (unsigned)NN) s0 = atomicAdd(&g_cur[c.x], 1);
        if ((unsigned)c.y < (unsigned)NN && (unsigned)r.y < (unsigned)NN) s1 = atomicAdd(&g_cur[c.y], 1);
        if ((unsigned)c.z < (unsigned)NN && (unsigned)r.z < (unsigned)NN) s2 = atomicAdd(&g_cur[c.z], 1);
        if ((unsigned)c.w < (unsigned)NN && (unsigned)r.w < (unsigned)NN) s3 = atomicAdd(&g_cur[c.w], 1);
        if (s0 >= 0) g_src[s0] = r.x;
        if (s1 >= 0) g_src[s1] = r.y;
        if (s2 >= 0) g_src[s2] = r.z;
        if (s3 >= 0) g_src[s3] = r.w;
    } else if (q == nQ) {
        for (int e = nQ * 4; e < nE; e++) {
            int rr = row[e], t = col[e];
            if ((unsigned)rr >= (unsigned)NN || (unsigned)t >= (unsigned)NN) continue;
            int slot = atomicAdd(&g_cur[t], 1);
            g_src[slot] = rr;
        }
    }
}

// ================= warp-aligned dense (R9 layout: coalesced weight loads) =================
// IN_MODE: 0=plain, 1=relu.  OUT_SCALE: multiply by dis[row].  OUT_HALF: fp16 output.
template <int K, int N, int NJ, int RPW, int WARPS, int IN_MODE, int OUT_SCALE, int OUT_HALF>
__global__ void __launch_bounds__(WARPS * 32)
k_dense_w(const float* __restrict__ in, const float* __restrict__ W,
          const float* __restrict__ bias, void* __restrict__ outv, int nRows) {
    constexpr int ROWS = WARPS * RPW;
    constexpr int KV = K / 4;
    __shared__ __align__(16) float s_in[ROWS][K];

    int r0  = blockIdx.x * ROWS;
    int tid = threadIdx.y * 32 + threadIdx.x;
    constexpr int NTH = WARPS * 32;

    const float4* in4 = (const float4*)in;
    for (int i = tid; i < ROWS * KV; i += NTH) {
        int r = i / KV;
        int c = i - r * KV;
        int gr = r0 + r;
        float4 v = make_float4(0.f, 0.f, 0.f, 0.f);
        if (gr < nRows) {
            v = in4[(size_t)gr * KV + c];
            if (IN_MODE == 1) {
                v.x = fmaxf(v.x, 0.f); v.y = fmaxf(v.y, 0.f);
                v.z = fmaxf(v.z, 0.f); v.w = fmaxf(v.w, 0.f);
            }
        }
        *(float4*)&s_in[r][c * 4] = v;
    }
    __syncthreads();

    int lane  = threadIdx.x;
    int rbase = threadIdx.y * RPW;

    float acc[RPW][NJ];
#pragma unroll
    for (int r = 0; r < RPW; r++)
#pragma unroll
        for (int jj = 0; jj < NJ; jj++) acc[r][jj] = 0.f;

#pragma unroll 2
    for (int k0 = 0; k0 < K; k0 += 4) {
        float wr[4][NJ];
#pragma unroll
        for (int kk = 0; kk < 4; kk++)
#pragma unroll
            for (int jj = 0; jj < NJ; jj++) {
                int j = lane + jj * 32;
                wr[kk][jj] = (j < N) ? __ldg(&W[(size_t)(k0 + kk) * N + j]) : 0.f;
            }
#pragma unroll
        for (int r = 0; r < RPW; r++) {
            float4 a = *(const float4*)&s_in[rbase + r][k0];  // warp broadcast
#pragma unroll
            for (int jj = 0; jj < NJ; jj++)
                acc[r][jj] = fmaf(a.x, wr[0][jj], fmaf(a.y, wr[1][jj],
                             fmaf(a.z, wr[2][jj], fmaf(a.w, wr[3][jj], acc[r][jj]))));
        }
    }

    float bv[NJ];
#pragma unroll
    for (int jj = 0; jj < NJ; jj++) {
        int j = lane + jj * 32;
        bv[jj] = (bias != nullptr && j < N) ? __ldg(&bias[j]) : 0.f;
    }
#pragma unroll
    for (int r = 0; r < RPW; r++) {
        int gr = r0 + rbase + r;
        if (gr < nRows) {
            float d = OUT_SCALE ? g_dis[gr] : 1.f;
#pragma unroll
            for (int jj = 0; jj < NJ; jj++) {
                int j = lane + jj * 32;
                if (j < N) {
                    float v = (acc[r][jj] + bv[jj]) * d;
                    if (OUT_HALF)
                        ((__half*)outv)[(size_t)gr * N + j] = __float2half(v);
                    else
                        ((float*)outv)[(size_t)gr * N + j] = v;
                }
            }
        }
    }
}

// ======== old-style dense (FC: N=16 divides warps cleanly) ========
template <int K, int N, int G, int RPB, int IN_MODE>
__global__ void k_dense(const float* __restrict__ in, const float* __restrict__ W,
                        const float* __restrict__ bias, float* __restrict__ out,
                        int nRows) {
    constexpr int ROWS = G * RPB;
    __shared__ __align__(16) float s_in[ROWS][K];

    int r0  = blockIdx.x * ROWS;
    int tid = threadIdx.y * N + threadIdx.x;
    int nth = N * G;

    for (int i = tid; i < ROWS * K; i += nth) {
        int r = i / K;
        int k = i - r * K;
        int gr = r0 + r;
        float v = 0.f;
        if (gr < nRows) {
            v = in[(size_t)gr * K + k];
            if (IN_MODE == 1) v = fmaxf(v, 0.f);
        }
        s_in[r][k] = v;
    }
    __syncthreads();

    int j     = threadIdx.x;
    int rbase = threadIdx.y * RPB;

    float acc[RPB];
#pragma unroll
    for (int r = 0; r < RPB; r++) acc[r] = 0.f;

#pragma unroll 4
    for (int k0 = 0; k0 < K; k0 += 4) {
        float w0 = __ldg(&W[(size_t)(k0 + 0) * N + j]);
        float w1 = __ldg(&W[(size_t)(k0 + 1) * N + j]);
        float w2 = __ldg(&W[(size_t)(k0 + 2) * N + j]);
        float w3 = __ldg(&W[(size_t)(k0 + 3) * N + j]);
#pragma unroll
        for (int r = 0; r < RPB; r++) {
            float4 a = *(const float4*)&s_in[rbase + r][k0];
            acc[r] = fmaf(a.x, w0, fmaf(a.y, w1, fmaf(a.z, w2, fmaf(a.w, w3, acc[r]))));
        }
    }

    float b = (bias != nullptr) ? __ldg(&bias[j]) : 0.f;
#pragma unroll
    for (int r = 0; r < RPB; r++) {
        int gr = r0 + rbase + r;
        if (gr < nRows) out[(size_t)gr * N + j] = acc[r] + b;
    }
}

// ================= CSR gather aggregation, fp16 payload (warp per node) =================
// Each active lane handles 4 features = one uint2 (2x half2) per row.
// acc(fp32) = y[node] + sum_{r} y[r]
// MODE 1: out(fp16) = d * relu(d * acc + bias)
// MODE 2: out(fp32) = d * acc
template <int C4, int MODE>
__global__ void __launch_bounds__(256)
k_gather_h(const __half* __restrict__ y, const float* __restrict__ bias,
           void* __restrict__ outv, int nN) {
    int node = blockIdx.x * blockDim.y + threadIdx.y;
    if (node >= nN) return;
    int lane  = threadIdx.x;
    int start = g_off[node];
    int cnt   = g_deg[node];
    bool act  = (lane < C4);

    float4 acc = make_float4(0.f, 0.f, 0.f, 0.f);
    if (act) {
        uint2 u = __ldg((const uint2*)(y + (size_t)node * H1) + lane);
        float2 f0 = __half22float2(*(const __half2*)&u.x);
        float2 f1 = __half22float2(*(const __half2*)&u.y);
        acc = make_float4(f0.x, f0.y, f1.x, f1.y);
    }

    int j = 0;
    for (; j + 8 <= cnt; j += 8) {
        int rr[8];
#pragma unroll
        for (int u = 0; u < 8; u++) rr[u] = __ldg(&g_src[start + j + u]);
#pragma unroll
        for (int u = 0; u < 8; u++) {
            if (act) {
                uint2 w = __ldg((const uint2*)(y + (size_t)rr[u] * H1) + lane);
                float2 f0 = __half22float2(*(const __half2*)&w.x);
                float2 f1 = __half22float2(*(const __half2*)&w.y);
                acc.x += f0.x; acc.y += f0.y; acc.z += f1.x; acc.w += f1.y;
            }
        }
    }
    if (j + 4 <= cnt) {
        int rr[4];
#pragma unroll
        for (int u = 0; u < 4; u++) rr[u] = __ldg(&g_src[start + j + u]);
#pragma unroll
        for (int u = 0; u < 4; u++) {
            if (act) {
                uint2 w = __ldg((const uint2*)(y + (size_t)rr[u] * H1) + lane);
                float2 f0 = __half22float2(*(const __half2*)&w.x);
                float2 f1 = __half22float2(*(const __half2*)&w.y);
                acc.x += f0.x; acc.y += f0.y; acc.z += f1.x; acc.w += f1.y;
            }
        }
        j += 4;
    }
    for (; j < cnt; j++) {
        int r = __ldg(&g_src[start + j]);
        if (act) {
            uint2 w = __ldg((const uint2*)(y + (size_t)r * H1) + lane);
            float2 f0 = __half22float2(*(const __half2*)&w.x);
            float2 f1 = __half22float2(*(const __half2*)&w.y);
            acc.x += f0.x; acc.y += f0.y; acc.z += f1.x; acc.w += f1.y;
        }
    }

    if (act) {
        float d = g_dis[node];
        if (MODE == 1) {
            float4 b = *(const float4*)&bias[lane * 4];
            float o0 = d * fmaxf(fmaf(d, acc.x, b.x), 0.f);
            float o1 = d * fmaxf(fmaf(d, acc.y, b.y), 0.f);
            float o2 = d * fmaxf(fmaf(d, acc.z, b.z), 0.f);
            float o3 = d * fmaxf(fmaf(d, acc.w, b.w), 0.f);
            __half2 h0 = __floats2half2_rn(o0, o1);
            __half2 h1 = __floats2half2_rn(o2, o3);
            uint2 u;
            u.x = *(const unsigned*)&h0;
            u.y = *(const unsigned*)&h1;
            ((uint2*)((__half*)outv + (size_t)node * H1))[lane] = u;
        } else {
            float4 o;
            o.x = d * acc.x; o.y = d * acc.y; o.z = d * acc.z; o.w = d * acc.w;
            ((float4*)outv)[(size_t)node * C4 + lane] = o;
        }
    }
}

// ================= launch =================
extern "C" void kernel_launch(void* const* d_in, const int* in_sizes, int n_in,
                              void* d_out, int out_size) {
    const float* x   = (const float*)d_in[0];
    const int*   ei  = (const int*)d_in[1];
    const float* W1  = (const float*)d_in[2];
    const float* b1  = (const float*)d_in[3];
    const float* W2  = (const float*)d_in[4];
    const float* b2  = (const float*)d_in[5];
    const float* Wfc = (const float*)d_in[6];
    const float* bfc = (const float*)d_in[7];
    float*       out = (float*)d_out;

    int nN = in_sizes[0] / FIN;
    int nE = in_sizes[1] / 2;
    const int* rowI = ei;
    const int* colI = ei + nE;

    __half *p_y1h, *p_y2h;
    float  *p_s2, *p_xw2;
    int    *p_deg, *p_total;
    cudaGetSymbolAddress((void**)&p_y1h,  g_y1h);
    cudaGetSymbolAddress((void**)&p_y2h,  g_y2h);
    cudaGetSymbolAddress((void**)&p_s2,   g_s2);
    cudaGetSymbolAddress((void**)&p_xw2,  g_xw2);
    cudaGetSymbolAddress((void**)&p_deg,  g_deg);
    cudaGetSymbolAddress((void**)&p_total, g_total);

    // --- degree + CSR build ---
    cudaMemsetAsync(p_deg, 0, (size_t)nN * sizeof(int));
    cudaMemsetAsync(p_total, 0, sizeof(int));
    {
        int nQ = nE / 4 + 1;
        k_count_deg<<<(nQ + 255) / 256, 256>>>(colI, nE);
        k_assign   <<<(nN + 255) / 256, 256>>>(nN);
        k_fill     <<<(nQ + 255) / 256, 256>>>(rowI, colI, nE);
    }

    // --- layer 1: y1h = fp16( d_r ⊙ (x @ W1) ) ---
    k_dense_w<FIN, H1, 4, 8, 8, 0, 1, 1><<<(nN + 63) / 64, dim3(32, 8)>>>(
        x, W1, nullptr, p_y1h, nN);

    // --- agg1 + mid fused: y2h = fp16( d ⊙ relu(d ⊙ (y1_self + Σ y1[src]) + b1) ) ---
    k_gather_h<C4_H1, 1><<<(nN + 7) / 8, dim3(32, 8)>>>(
        p_y1h, b1, p_y2h, nN);

    // --- agg2 (commuted before GEMM): s2 = fp32( d ⊙ (y2_self + Σ y2[src]) ) ---
    k_gather_h<C4_H1, 2><<<(nN + 7) / 8, dim3(32, 8)>>>(
        p_y2h, nullptr, p_s2, nN);

    // --- layer 2 GEMM: xw2 = s2 @ W2 + b2 ---
    k_dense_w<H1, H2, 7, 8, 8, 0, 0, 0><<<(nN + 63) / 64, dim3(32, 8)>>>(
        p_s2, W2, b2, p_xw2, nN);

    // --- FC: out = relu(xw2) @ Wfc + bfc ---
    k_dense<H2, FOUT, 8, 4, 1><<<(nN + 31) / 32, dim3(FOUT, 8)>>>(
        p_xw2, Wfc, bfc, out, nN);
}

// round 12
// speedup vs baseline: 2.2672x; 1.0894x over previous
#include <cuda_runtime.h>
#include <cuda_fp16.h>
#include <mma.h>
#include <cstddef>

using namespace nvcuda;

#define NN 50000
#define NE_MAX 800000
#define FIN 128
#define H1 100
#define H2 200
#define FOUT 16
#define C4_H1 (H1 / 4)   // 25 4-float chunks per row

// -------- scratch (static device globals; no allocation) --------
__device__ __align__(16) int    g_deg[NN];
__device__ __align__(16) float  g_dis[NN];
__device__ __align__(16) int    g_off[NN];
__device__ __align__(16) int    g_cur[NN];
__device__               int    g_total;
__device__ __align__(16) int    g_src[NE_MAX];
__device__ __align__(16) __half g_w1h[128 * 120];        // W1 fp16, N padded 100->120
__device__ __align__(16) __half g_y1h[(size_t)NN * H1];  // fp16 gather payload 1
__device__ __align__(16) __half g_y2h[(size_t)NN * H1];  // fp16 gather payload 2
__device__ __align__(16) float  g_s2 [(size_t)NN * H1];  // fp32 dense2 input
__device__ __align__(16) float  g_xw2[(size_t)NN * H2];

// ================= degree / CSR build =================
__global__ void k_count_deg(const int* __restrict__ col, int nE) {
    int q = blockIdx.x * blockDim.x + threadIdx.x;
    int nQ = nE >> 2;
    if (q < nQ) {
        int4 c = *(const int4*)(col + q * 4);
        if ((unsigned)c.x < (unsigned)NN) atomicAdd(&g_deg[c.x], 1);
        if ((unsigned)c.y < (unsigned)NN) atomicAdd(&g_deg[c.y], 1);
        if ((unsigned)c.z < (unsigned)NN) atomicAdd(&g_deg[c.z], 1);
        if ((unsigned)c.w < (unsigned)NN) atomicAdd(&g_deg[c.w], 1);
    } else if (q == nQ) {
        for (int e = nQ * 4; e < nE; e++) {
            int t = col[e];
            if ((unsigned)t < (unsigned)NN) atomicAdd(&g_deg[t], 1);
        }
    }
}

__global__ void k_assign(int n) {
    int i = blockIdx.x * blockDim.x + threadIdx.x;
    if (i >= n) return;
    int d = g_deg[i];
    g_dis[i] = rsqrtf((float)(d + 1));
    int off = atomicAdd(&g_total, d);
    g_off[i] = off;
    g_cur[i] = off;
}

__global__ void k_fill(const int* __restrict__ row, const int* __restrict__ col, int nE) {
    int q = blockIdx.x * blockDim.x + threadIdx.x;
    int nQ = nE >> 2;
    if (q < nQ) {
        int4 r = *(const int4*)(row + q * 4);
        int4 c = *(const int4*)(col + q * 4);
        int s0 = -1, s1 = -1, s2 = -1, s3 = -1;
        if ((unsigned)c.x < (unsigned)NN && (unsigned)r.x < (unsigned)NN) s0 = atomicAdd(&g_cur[c.x], 1);
        if ((unsigned)c.y < (unsigned)NN && (unsigned)r.y < (unsigned)NN) s1 = atomicAdd(&g_cur[c.y], 1);
        if ((unsigned)c.z < (unsigned)NN && (unsigned)r.z < (unsigned)NN) s2 = atomicAdd(&g_cur[c.z], 1);
        if ((unsigned)c.w < (unsigned)NN && (unsigned)r.w < (unsigned)NN) s3 = atomicAdd(&g_cur[c.w], 1);
        if (s0 >= 0) g_src[s0] = r.x;
        if (s1 >= 0) g_src[s1] = r.y;
        if (s2 >= 0) g_src[s2] = r.z;
        if (s3 >= 0) g_src[s3] = r.w;
    } else if (q == nQ) {
        for (int e = nQ * 4; e < nE; e++) {
            int rr = row[e], t = col[e];
            if ((unsigned)rr >= (unsigned)NN || (unsigned)t >= (unsigned)NN) continue;
            int slot = atomicAdd(&g_cur[t], 1);
            g_src[slot] = rr;
        }
    }
}

// ================= W1 -> fp16, zero-padded to [128][120] =================
__global__ void k_conv_w1(const float* __restrict__ W1) {
    int idx = blockIdx.x * blockDim.x + threadIdx.x;
    if (idx >= 128 * 120) return;
    int k = idx / 120;
    int j = idx - k * 120;
    g_w1h[idx] = __float2half((j < H1) ? W1[(size_t)k * H1 + j] : 0.f);
}

// ================= dense1 via WMMA (fp16 in, fp32 acc, fp16 out scaled by dis) =================
// Block: 64 rows, 4 warps (warp = 16 rows). y1h[r][j] = fp16( dis[r] * (x[r] . W1[:,j]) )
__global__ void __launch_bounds__(128)
k_dense1_wmma(const float* __restrict__ x, __half* __restrict__ y1h, int nRows) {
    __shared__ __align__(16) __half s_x[64 * 128];   // 16 KB
    __shared__ __align__(16) __half s_w[128 * 120];  // 30 KB

    int tid  = threadIdx.x;
    int warp = tid >> 5;
    int lane = tid & 31;
    int r0   = blockIdx.x * 64;

    // load + convert x tile (fp32 -> fp16)
    const float4* x4 = (const float4*)x;
    for (int i = tid; i < 64 * 32; i += 128) {   // 32 float4 per row
        int r = i >> 5, c = i & 31;
        int gr = r0 + r;
        float4 v = (gr < nRows) ? x4[(size_t)gr * 32 + c] : make_float4(0.f, 0.f, 0.f, 0.f);
        __half2 h0 = __floats2half2_rn(v.x, v.y);
        __half2 h1 = __floats2half2_rn(v.z, v.w);
        uint2 u = make_uint2(*(unsigned*)&h0, *(unsigned*)&h1);
        *(uint2*)&s_x[r * 128 + c * 4] = u;
    }
    // load fp16 weights (1920 int4)
    {
        const int4* wsrc = (const int4*)g_w1h;
        int4* wdst = (int4*)s_w;
        for (int i = tid; i < 1920; i += 128) wdst[i] = wsrc[i];
    }
    __syncthreads();

    // cache A fragments (this warp's 16 rows, all K)
    wmma::fragment<wmma::matrix_a, 16, 16, 16, __half, wmma::row_major> afrag[8];
#pragma unroll
    for (int k = 0; k < 8; k++)
        wmma::load_matrix_sync(afrag[k], &s_x[(warp * 16) * 128 + k * 16], 128);
    __syncthreads();   // s_x now reusable as epilogue scratch

    float* s_c = (float*)s_x + warp * 256;   // 16x16 per-warp tile

    for (int n = 0; n < 7; n++) {            // 7 N-tiles cover 112 >= 100
        wmma::fragment<wmma::accumulator, 16, 16, 16, float> acc;
        wmma::fill_fragment(acc, 0.f);
#pragma unroll
        for (int k = 0; k < 8; k++) {
            wmma::fragment<wmma::matrix_b, 16, 16, 16, __half, wmma::row_major> bfrag;
            wmma::load_matrix_sync(bfrag, &s_w[(k * 16) * 120 + n * 16], 120);
            wmma::mma_sync(acc, afrag[k], bfrag, acc);
        }
        wmma::store_matrix_sync(s_c, acc, 16, wmma::mem_row_major);
        __syncwarp();
        // epilogue: scale by dis[row], write half2 pairs with bounds
        for (int i = lane; i < 128; i += 32) {   // 16 rows x 8 pairs
            int r = i >> 3, p = i & 7;
            int gr = r0 + warp * 16 + r;
            int gc = n * 16 + p * 2;
            if (gr < nRows && gc < H1) {
                float d = g_dis[gr];
                __half2 h = __floats2half2_rn(s_c[r * 16 + p * 2] * d,
                                              s_c[r * 16 + p * 2 + 1] * d);
                *(unsigned*)&y1h[(size_t)gr * H1 + gc] = *(unsigned*)&h;
            }
        }
        __syncwarp();
    }
}

// ================= warp-aligned dense (dense2, fp32) =================
template <int K, int N, int NJ, int RPW, int WARPS, int IN_MODE, int OUT_SCALE>
__global__ void __launch_bounds__(WARPS * 32)
k_dense_w(const float* __restrict__ in, const float* __restrict__ W,
          const float* __restrict__ bias, float* __restrict__ out, int nRows) {
    constexpr int ROWS = WARPS * RPW;
    constexpr int KV = K / 4;
    __shared__ __align__(16) float s_in[ROWS][K];

    int r0  = blockIdx.x * ROWS;
    int tid = threadIdx.y * 32 + threadIdx.x;
    constexpr int NTH = WARPS * 32;

    const float4* in4 = (const float4*)in;
    for (int i = tid; i < ROWS * KV; i += NTH) {
        int r = i / KV;
        int c = i - r * KV;
        int gr = r0 + r;
        float4 v = make_float4(0.f, 0.f, 0.f, 0.f);
        if (gr < nRows) {
            v = in4[(size_t)gr * KV + c];
            if (IN_MODE == 1) {
                v.x = fmaxf(v.x, 0.f); v.y = fmaxf(v.y, 0.f);
                v.z = fmaxf(v.z, 0.f); v.w = fmaxf(v.w, 0.f);
            }
        }
        *(float4*)&s_in[r][c * 4] = v;
    }
    __syncthreads();

    int lane  = threadIdx.x;
    int rbase = threadIdx.y * RPW;

    float acc[RPW][NJ];
#pragma unroll
    for (int r = 0; r < RPW; r++)
#pragma unroll
        for (int jj = 0; jj < NJ; jj++) acc[r][jj] = 0.f;

#pragma unroll 2
    for (int k0 = 0; k0 < K; k0 += 4) {
        float wr[4][NJ];
#pragma unroll
        for (int kk = 0; kk < 4; kk++)
#pragma unroll
            for (int jj = 0; jj < NJ; jj++) {
                int j = lane + jj * 32;
                wr[kk][jj] = (j < N) ? __ldg(&W[(size_t)(k0 + kk) * N + j]) : 0.f;
            }
#pragma unroll
        for (int r = 0; r < RPW; r++) {
            float4 a = *(const float4*)&s_in[rbase + r][k0];
#pragma unroll
            for (int jj = 0; jj < NJ; jj++)
                acc[r][jj] = fmaf(a.x, wr[0][jj], fmaf(a.y, wr[1][jj],
                             fmaf(a.z, wr[2][jj], fmaf(a.w, wr[3][jj], acc[r][jj]))));
        }
    }

    float bv[NJ];
#pragma unroll
    for (int jj = 0; jj < NJ; jj++) {
        int j = lane + jj * 32;
        bv[jj] = (bias != nullptr && j < N) ? __ldg(&bias[j]) : 0.f;
    }
#pragma unroll
    for (int r = 0; r < RPW; r++) {
        int gr = r0 + rbase + r;
        if (gr < nRows) {
            float d = OUT_SCALE ? g_dis[gr] : 1.f;
#pragma unroll
            for (int jj = 0; jj < NJ; jj++) {
                int j = lane + jj * 32;
                if (j < N) out[(size_t)gr * N + j] = (acc[r][jj] + bv[jj]) * d;
            }
        }
    }
}

// ======== old-style dense (FC) ========
template <int K, int N, int G, int RPB, int IN_MODE>
__global__ void k_dense(const float* __restrict__ in, const float* __restrict__ W,
                        const float* __restrict__ bias, float* __restrict__ out,
                        int nRows) {
    constexpr int ROWS = G * RPB;
    __shared__ __align__(16) float s_in[ROWS][K];

    int r0  = blockIdx.x * ROWS;
    int tid = threadIdx.y * N + threadIdx.x;
    int nth = N * G;

    for (int i = tid; i < ROWS * K; i += nth) {
        int r = i / K;
        int k = i - r * K;
        int gr = r0 + r;
        float v = 0.f;
        if (gr < nRows) {
            v = in[(size_t)gr * K + k];
            if (IN_MODE == 1) v = fmaxf(v, 0.f);
        }
        s_in[r][k] = v;
    }
    __syncthreads();

    int j     = threadIdx.x;
    int rbase = threadIdx.y * RPB;

    float acc[RPB];
#pragma unroll
    for (int r = 0; r < RPB; r++) acc[r] = 0.f;

#pragma unroll 4
    for (int k0 = 0; k0 < K; k0 += 4) {
        float w0 = __ldg(&W[(size_t)(k0 + 0) * N + j]);
        float w1 = __ldg(&W[(size_t)(k0 + 1) * N + j]);
        float w2 = __ldg(&W[(size_t)(k0 + 2) * N + j]);
        float w3 = __ldg(&W[(size_t)(k0 + 3) * N + j]);
#pragma unroll
        for (int r = 0; r < RPB; r++) {
            float4 a = *(const float4*)&s_in[rbase + r][k0];
            acc[r] = fmaf(a.x, w0, fmaf(a.y, w1, fmaf(a.z, w2, fmaf(a.w, w3, acc[r]))));
        }
    }

    float b = (bias != nullptr) ? __ldg(&bias[j]) : 0.f;
#pragma unroll
    for (int r = 0; r < RPB; r++) {
        int gr = r0 + rbase + r;
        if (gr < nRows) out[(size_t)gr * N + j] = acc[r] + b;
    }
}

// ================= CSR gather aggregation, fp16 payload =================
template <int C4, int MODE>
__global__ void __launch_bounds__(256)
k_gather_h(const __half* __restrict__ y, const float* __restrict__ bias,
           void* __restrict__ outv, int nN) {
    int node = blockIdx.x * blockDim.y + threadIdx.y;
    if (node >= nN) return;
    int lane  = threadIdx.x;
    int start = g_off[node];
    int cnt   = g_deg[node];
    bool act  = (lane < C4);

    float4 acc = make_float4(0.f, 0.f, 0.f, 0.f);
    if (act) {
        uint2 u = __ldg((const uint2*)(y + (size_t)node * H1) + lane);
        float2 f0 = __half22float2(*(const __half2*)&u.x);
        float2 f1 = __half22float2(*(const __half2*)&u.y);
        acc = make_float4(f0.x, f0.y, f1.x, f1.y);
    }

    int j = 0;
    for (; j + 8 <= cnt; j += 8) {
        int rr[8];
#pragma unroll
        for (int u = 0; u < 8; u++) rr[u] = __ldg(&g_src[start + j + u]);
#pragma unroll
        for (int u = 0; u < 8; u++) {
            if (act) {
                uint2 w = __ldg((const uint2*)(y + (size_t)rr[u] * H1) + lane);
                float2 f0 = __half22float2(*(const __half2*)&w.x);
                float2 f1 = __half22float2(*(const __half2*)&w.y);
                acc.x += f0.x; acc.y += f0.y; acc.z += f1.x; acc.w += f1.y;
            }
        }
    }
    if (j + 4 <= cnt) {
        int rr[4];
#pragma unroll
        for (int u = 0; u < 4; u++) rr[u] = __ldg(&g_src[start + j + u]);
#pragma unroll
        for (int u = 0; u < 4; u++) {
            if (act) {
                uint2 w = __ldg((const uint2*)(y + (size_t)rr[u] * H1) + lane);
                float2 f0 = __half22float2(*(const __half2*)&w.x);
                float2 f1 = __half22float2(*(const __half2*)&w.y);
                acc.x += f0.x; acc.y += f0.y; acc.z += f1.x; acc.w += f1.y;
            }
        }
        j += 4;
    }
    for (; j < cnt; j++) {
        int r = __ldg(&g_src[start + j]);
        if (act) {
            uint2 w = __ldg((const uint2*)(y + (size_t)r * H1) + lane);
            float2 f0 = __half22float2(*(const __half2*)&w.x);
            float2 f1 = __half22float2(*(const __half2*)&w.y);
            acc.x += f0.x; acc.y += f0.y; acc.z += f1.x; acc.w += f1.y;
        }
    }

    if (act) {
        float d = g_dis[node];
        if (MODE == 1) {
            float4 b = *(const float4*)&bias[lane * 4];
            float o0 = d * fmaxf(fmaf(d, acc.x, b.x), 0.f);
            float o1 = d * fmaxf(fmaf(d, acc.y, b.y), 0.f);
            float o2 = d * fmaxf(fmaf(d, acc.z, b.z), 0.f);
            float o3 = d * fmaxf(fmaf(d, acc.w, b.w), 0.f);
            __half2 h0 = __floats2half2_rn(o0, o1);
            __half2 h1 = __floats2half2_rn(o2, o3);
            uint2 u;
            u.x = *(const unsigned*)&h0;
            u.y = *(const unsigned*)&h1;
            ((uint2*)((__half*)outv + (size_t)node * H1))[lane] = u;
        } else {
            float4 o;
            o.x = d * acc.x; o.y = d * acc.y; o.z = d * acc.z; o.w = d * acc.w;
            ((float4*)outv)[(size_t)node * C4 + lane] = o;
        }
    }
}

// ================= launch =================
extern "C" void kernel_launch(void* const* d_in, const int* in_sizes, int n_in,
                              void* d_out, int out_size) {
    const float* x   = (const float*)d_in[0];
    const int*   ei  = (const int*)d_in[1];
    const float* W1  = (const float*)d_in[2];
    const float* b1  = (const float*)d_in[3];
    const float* W2  = (const float*)d_in[4];
    const float* b2  = (const float*)d_in[5];
    const float* Wfc = (const float*)d_in[6];
    const float* bfc = (const float*)d_in[7];
    float*       out = (float*)d_out;

    int nN = in_sizes[0] / FIN;
    int nE = in_sizes[1] / 2;
    const int* rowI = ei;
    const int* colI = ei + nE;

    __half *p_y1h, *p_y2h;
    float  *p_s2, *p_xw2;
    int    *p_deg, *p_total;
    cudaGetSymbolAddress((void**)&p_y1h,  g_y1h);
    cudaGetSymbolAddress((void**)&p_y2h,  g_y2h);
    cudaGetSymbolAddress((void**)&p_s2,   g_s2);
    cudaGetSymbolAddress((void**)&p_xw2,  g_xw2);
    cudaGetSymbolAddress((void**)&p_deg,  g_deg);
    cudaGetSymbolAddress((void**)&p_total, g_total);

    // --- degree + CSR build ---
    cudaMemsetAsync(p_deg, 0, (size_t)nN * sizeof(int));
    cudaMemsetAsync(p_total, 0, sizeof(int));
    {
        int nQ = nE / 4 + 1;
        k_count_deg<<<(nQ + 255) / 256, 256>>>(colI, nE);
        k_assign   <<<(nN + 255) / 256, 256>>>(nN);
        k_fill     <<<(nQ + 255) / 256, 256>>>(rowI, colI, nE);
    }

    // --- W1 -> fp16 (padded) ---
    k_conv_w1<<<(128 * 120 + 255) / 256, 256>>>(W1);

    // --- layer 1 (WMMA): y1h = fp16( d_r ⊙ (x @ W1) ) ---
    k_dense1_wmma<<<(nN + 63) / 64, 128>>>(x, p_y1h, nN);

    // --- agg1 + mid fused: y2h = fp16( d ⊙ relu(d ⊙ (y1_self + Σ y1[src]) + b1) ) ---
    k_gather_h<C4_H1, 1><<<(nN + 7) / 8, dim3(32, 8)>>>(
        p_y1h, b1, p_y2h, nN);

    // --- agg2 (commuted before GEMM): s2 = fp32( d ⊙ (y2_self + Σ y2[src]) ) ---
    k_gather_h<C4_H1, 2><<<(nN + 7) / 8, dim3(32, 8)>>>(
        p_y2h, nullptr, p_s2, nN);

    // --- layer 2 GEMM: xw2 = s2 @ W2 + b2 ---
    k_dense_w<H1, H2, 7, 8, 8, 0, 0><<<(nN + 63) / 64, dim3(32, 8)>>>(
        p_s2, W2, b2, p_xw2, nN);

    // --- FC: out = relu(xw2) @ Wfc + bfc ---
    k_dense<H2, FOUT, 8, 4, 1><<<(nN + 31) / 32, dim3(FOUT, 8)>>>(
        p_xw2, Wfc, bfc, out, nN);
}

// round 13
// speedup vs baseline: 2.7125x; 1.1964x over previous
#include <cuda_runtime.h>
#include <cuda_fp16.h>
#include <mma.h>
#include <cstddef>

using namespace nvcuda;

#define NN 50000
#define NE_MAX 800000
#define FIN 128
#define H1 100
#define H2 200
#define FOUT 16
#define C4_H1 (H1 / 4)   // 25 4-float chunks per row

// -------- scratch (static device globals; no allocation) --------
__device__ __align__(16) int    g_deg[NN];
__device__ __align__(16) float  g_dis[NN];
__device__ __align__(16) int    g_off[NN];
__device__ __align__(16) int    g_cur[NN];
__device__               int    g_total;
__device__ __align__(16) int    g_src[NE_MAX];
__device__ __align__(16) __half g_w1h[128 * 120];        // W1 fp16, N padded 100->120
__device__ __align__(16) __half g_w2h[112 * 208];        // W2 fp16, K 100->112, N 200->208
__device__ __align__(16) __half g_y1h[(size_t)NN * H1];  // fp16 gather payload 1
__device__ __align__(16) __half g_y2h[(size_t)NN * H1];  // fp16 gather payload 2
__device__ __align__(16) __half g_s2h[(size_t)NN * H1];  // fp16 dense2 input
__device__ __align__(16) float  g_xw2[(size_t)NN * H2];

// ================= degree / CSR build =================
__global__ void k_count_deg(const int* __restrict__ col, int nE) {
    int q = blockIdx.x * blockDim.x + threadIdx.x;
    int nQ = nE >> 2;
    if (q < nQ) {
        int4 c = *(const int4*)(col + q * 4);
        if ((unsigned)c.x < (unsigned)NN) atomicAdd(&g_deg[c.x], 1);
        if ((unsigned)c.y < (unsigned)NN) atomicAdd(&g_deg[c.y], 1);
        if ((unsigned)c.z < (unsigned)NN) atomicAdd(&g_deg[c.z], 1);
        if ((unsigned)c.w < (unsigned)NN) atomicAdd(&g_deg[c.w], 1);
    } else if (q == nQ) {
        for (int e = nQ * 4; e < nE; e++) {
            int t = col[e];
            if ((unsigned)t < (unsigned)NN) atomicAdd(&g_deg[t], 1);
        }
    }
}

__global__ void k_assign(int n) {
    int i = blockIdx.x * blockDim.x + threadIdx.x;
    if (i >= n) return;
    int d = g_deg[i];
    g_dis[i] = rsqrtf((float)(d + 1));
    int off = atomicAdd(&g_total, d);
    g_off[i] = off;
    g_cur[i] = off;
}

__global__ void k_fill(const int* __restrict__ row, const int* __restrict__ col, int nE) {
    int q = blockIdx.x * blockDim.x + threadIdx.x;
    int nQ = nE >> 2;
    if (q < nQ) {
        int4 r = *(const int4*)(row + q * 4);
        int4 c = *(const int4*)(col + q * 4);
        int s0 = -1, s1 = -1, s2 = -1, s3 = -1;
        if ((unsigned)c.x < (unsigned)NN && (unsigned)r.x < (unsigned)NN) s0 = atomicAdd(&g_cur[c.x], 1);
        if ((unsigned)c.y < (unsigned)NN && (unsigned)r.y < (unsigned)NN) s1 = atomicAdd(&g_cur[c.y], 1);
        if ((unsigned)c.z < (unsigned)NN && (unsigned)r.z < (unsigned)NN) s2 = atomicAdd(&g_cur[c.z], 1);
        if ((unsigned)c.w < (unsigned)NN && (unsigned)r.w < (unsigned)NN) s3 = atomicAdd(&g_cur[c.w], 1);
        if (s0 >= 0) g_src[s0] = r.x;
        if (s1 >= 0) g_src[s1] = r.y;
        if (s2 >= 0) g_src[s2] = r.z;
        if (s3 >= 0) g_src[s3] = r.w;
    } else if (q == nQ) {
        for (int e = nQ * 4; e < nE; e++) {
            int rr = row[e], t = col[e];
            if ((unsigned)rr >= (unsigned)NN || (unsigned)t >= (unsigned)NN) continue;
            int slot = atomicAdd(&g_cur[t], 1);
            g_src[slot] = rr;
        }
    }
}

// ================= weight converts =================
__global__ void k_conv_w1(const float* __restrict__ W1) {
    int idx = blockIdx.x * blockDim.x + threadIdx.x;
    if (idx >= 128 * 120) return;
    int k = idx / 120;
    int j = idx - k * 120;
    g_w1h[idx] = __float2half((j < H1) ? W1[(size_t)k * H1 + j] : 0.f);
}

__global__ void k_conv_w2(const float* __restrict__ W2) {
    int idx = blockIdx.x * blockDim.x + threadIdx.x;
    if (idx >= 112 * 208) return;
    int k = idx / 208;
    int j = idx - k * 208;
    g_w2h[idx] = __float2half((k < H1 && j < H2) ? W2[(size_t)k * H2 + j] : 0.f);
}

// ================= dense1 via WMMA (fp16 in, fp32 acc, fp16 out scaled by dis) =================
__global__ void __launch_bounds__(128)
k_dense1_wmma(const float* __restrict__ x, __half* __restrict__ y1h, int nRows) {
    __shared__ __align__(16) __half s_x[64 * 128];   // 16 KB
    __shared__ __align__(16) __half s_w[128 * 120];  // 30 KB

    int tid  = threadIdx.x;
    int warp = tid >> 5;
    int lane = tid & 31;
    int r0   = blockIdx.x * 64;

    const float4* x4 = (const float4*)x;
    for (int i = tid; i < 64 * 32; i += 128) {
        int r = i >> 5, c = i & 31;
        int gr = r0 + r;
        float4 v = (gr < nRows) ? x4[(size_t)gr * 32 + c] : make_float4(0.f, 0.f, 0.f, 0.f);
        __half2 h0 = __floats2half2_rn(v.x, v.y);
        __half2 h1 = __floats2half2_rn(v.z, v.w);
        uint2 u = make_uint2(*(unsigned*)&h0, *(unsigned*)&h1);
        *(uint2*)&s_x[r * 128 + c * 4] = u;
    }
    {
        const int4* wsrc = (const int4*)g_w1h;
        int4* wdst = (int4*)s_w;
        for (int i = tid; i < 1920; i += 128) wdst[i] = wsrc[i];
    }
    __syncthreads();

    wmma::fragment<wmma::matrix_a, 16, 16, 16, __half, wmma::row_major> afrag[8];
#pragma unroll
    for (int k = 0; k < 8; k++)
        wmma::load_matrix_sync(afrag[k], &s_x[(warp * 16) * 128 + k * 16], 128);
    __syncthreads();

    float* s_c = (float*)s_x + warp * 256;

    for (int n = 0; n < 7; n++) {
        wmma::fragment<wmma::accumulator, 16, 16, 16, float> acc;
        wmma::fill_fragment(acc, 0.f);
#pragma unroll
        for (int k = 0; k < 8; k++) {
            wmma::fragment<wmma::matrix_b, 16, 16, 16, __half, wmma::row_major> bfrag;
            wmma::load_matrix_sync(bfrag, &s_w[(k * 16) * 120 + n * 16], 120);
            wmma::mma_sync(acc, afrag[k], bfrag, acc);
        }
        wmma::store_matrix_sync(s_c, acc, 16, wmma::mem_row_major);
        __syncwarp();
        for (int i = lane; i < 128; i += 32) {
            int r = i >> 3, p = i & 7;
            int gr = r0 + warp * 16 + r;
            int gc = n * 16 + p * 2;
            if (gr < nRows && gc < H1) {
                float d = g_dis[gr];
                __half2 h = __floats2half2_rn(s_c[r * 16 + p * 2] * d,
                                              s_c[r * 16 + p * 2 + 1] * d);
                *(unsigned*)&y1h[(size_t)gr * H1 + gc] = *(unsigned*)&h;
            }
        }
        __syncwarp();
    }
}

// ================= dense2 via WMMA: xw2 = s2h @ W2 + b2 (fp32 out) =================
// A: s2h rows padded K 100->112 in smem. B: g_w2h [112][208] fragments from global (L1-hot).
__global__ void __launch_bounds__(128)
k_dense2_wmma(const __half* __restrict__ s2h, const float* __restrict__ b2,
              float* __restrict__ xw2, int nRows) {
    __shared__ __align__(16) __half s_a[64 * 112];   // 14 KB
    __shared__ __align__(16) float  s_c4[4 * 256];   // per-warp epilogue scratch

    int tid  = threadIdx.x;
    int warp = tid >> 5;
    int lane = tid & 31;
    int r0   = blockIdx.x * 64;

    // load s2h tile: 25 uint2 chunks (100 halves) per row, pad cols 100..111 with 0
    for (int i = tid; i < 64 * 28; i += 128) {   // 28 chunks of 4 halves = 112
        int r = i / 28, c = i - r * 28;
        int gr = r0 + r;
        uint2 u = make_uint2(0u, 0u);
        if (gr < nRows && c < 25)
            u = __ldg((const uint2*)(s2h + (size_t)gr * H1) + c);
        *(uint2*)&s_a[r * 112 + c * 4] = u;
    }
    __syncthreads();

    wmma::fragment<wmma::matrix_a, 16, 16, 16, __half, wmma::row_major> afrag[7];
#pragma unroll
    for (int k = 0; k < 7; k++)
        wmma::load_matrix_sync(afrag[k], &s_a[(warp * 16) * 112 + k * 16], 112);

    float* s_c = s_c4 + warp * 256;

    for (int n = 0; n < 13; n++) {               // 13 x 16 = 208 >= 200
        wmma::fragment<wmma::accumulator, 16, 16, 16, float> acc;
        wmma::fill_fragment(acc, 0.f);
#pragma unroll
        for (int k = 0; k < 7; k++) {
            wmma::fragment<wmma::matrix_b, 16, 16, 16, __half, wmma::row_major> bfrag;
            wmma::load_matrix_sync(bfrag, &g_w2h[(k * 16) * 208 + n * 16], 208);
            wmma::mma_sync(acc, afrag[k], bfrag, acc);
        }
        wmma::store_matrix_sync(s_c, acc, 16, wmma::mem_row_major);
        __syncwarp();
        for (int i = lane; i < 128; i += 32) {   // 16 rows x 8 pairs
            int r = i >> 3, p = i & 7;
            int gr = r0 + warp * 16 + r;
            int gc = n * 16 + p * 2;
            if (gr < nRows && gc < H2) {
                float2 o;
                o.x = s_c[r * 16 + p * 2]     + __ldg(&b2[gc]);
                o.y = s_c[r * 16 + p * 2 + 1] + __ldg(&b2[gc + 1]);
                *(float2*)&xw2[(size_t)gr * H2 + gc] = o;
            }
        }
        __syncwarp();
    }
}

// ======== old-style dense (FC) ========
template <int K, int N, int G, int RPB, int IN_MODE>
__global__ void k_dense(const float* __restrict__ in, const float* __restrict__ W,
                        const float* __restrict__ bias, float* __restrict__ out,
                        int nRows) {
    constexpr int ROWS = G * RPB;
    __shared__ __align__(16) float s_in[ROWS][K];

    int r0  = blockIdx.x * ROWS;
    int tid = threadIdx.y * N + threadIdx.x;
    int nth = N * G;

    for (int i = tid; i < ROWS * K; i += nth) {
        int r = i / K;
        int k = i - r * K;
        int gr = r0 + r;
        float v = 0.f;
        if (gr < nRows) {
            v = in[(size_t)gr * K + k];
            if (IN_MODE == 1) v = fmaxf(v, 0.f);
        }
        s_in[r][k] = v;
    }
    __syncthreads();

    int j     = threadIdx.x;
    int rbase = threadIdx.y * RPB;

    float acc[RPB];
#pragma unroll
    for (int r = 0; r < RPB; r++) acc[r] = 0.f;

#pragma unroll 4
    for (int k0 = 0; k0 < K; k0 += 4) {
        float w0 = __ldg(&W[(size_t)(k0 + 0) * N + j]);
        float w1 = __ldg(&W[(size_t)(k0 + 1) * N + j]);
        float w2 = __ldg(&W[(size_t)(k0 + 2) * N + j]);
        float w3 = __ldg(&W[(size_t)(k0 + 3) * N + j]);
#pragma unroll
        for (int r = 0; r < RPB; r++) {
            float4 a = *(const float4*)&s_in[rbase + r][k0];
            acc[r] = fmaf(a.x, w0, fmaf(a.y, w1, fmaf(a.z, w2, fmaf(a.w, w3, acc[r]))));
        }
    }

    float b = (bias != nullptr) ? __ldg(&bias[j]) : 0.f;
#pragma unroll
    for (int r = 0; r < RPB; r++) {
        int gr = r0 + rbase + r;
        if (gr < nRows) out[(size_t)gr * N + j] = acc[r] + b;
    }
}

// ================= CSR gather aggregation, fp16 payload =================
// MODE 1: out(fp16) = d * relu(d * acc + bias)
// MODE 2: out(fp16) = d * acc
template <int C4, int MODE>
__global__ void __launch_bounds__(256)
k_gather_h(const __half* __restrict__ y, const float* __restrict__ bias,
           __half* __restrict__ outh, int nN) {
    int node = blockIdx.x * blockDim.y + threadIdx.y;
    if (node >= nN) return;
    int lane  = threadIdx.x;
    int start = g_off[node];
    int cnt   = g_deg[node];
    bool act  = (lane < C4);

    float4 acc = make_float4(0.f, 0.f, 0.f, 0.f);
    if (act) {
        uint2 u = __ldg((const uint2*)(y + (size_t)node * H1) + lane);
        float2 f0 = __half22float2(*(const __half2*)&u.x);
        float2 f1 = __half22float2(*(const __half2*)&u.y);
        acc = make_float4(f0.x, f0.y, f1.x, f1.y);
    }

    int j = 0;
    for (; j + 8 <= cnt; j += 8) {
        int rr[8];
#pragma unroll
        for (int u = 0; u < 8; u++) rr[u] = __ldg(&g_src[start + j + u]);
#pragma unroll
        for (int u = 0; u < 8; u++) {
            if (act) {
                uint2 w = __ldg((const uint2*)(y + (size_t)rr[u] * H1) + lane);
                float2 f0 = __half22float2(*(const __half2*)&w.x);
                float2 f1 = __half22float2(*(const __half2*)&w.y);
                acc.x += f0.x; acc.y += f0.y; acc.z += f1.x; acc.w += f1.y;
            }
        }
    }
    if (j + 4 <= cnt) {
        int rr[4];
#pragma unroll
        for (int u = 0; u < 4; u++) rr[u] = __ldg(&g_src[start + j + u]);
#pragma unroll
        for (int u = 0; u < 4; u++) {
            if (act) {
                uint2 w = __ldg((const uint2*)(y + (size_t)rr[u] * H1) + lane);
                float2 f0 = __half22float2(*(const __half2*)&w.x);
                float2 f1 = __half22float2(*(const __half2*)&w.y);
                acc.x += f0.x; acc.y += f0.y; acc.z += f1.x; acc.w += f1.y;
            }
        }
        j += 4;
    }
    for (; j < cnt; j++) {
        int r = __ldg(&g_src[start + j]);
        if (act) {
            uint2 w = __ldg((const uint2*)(y + (size_t)r * H1) + lane);
            float2 f0 = __half22float2(*(const __half2*)&w.x);
            float2 f1 = __half22float2(*(const __half2*)&w.y);
            acc.x += f0.x; acc.y += f0.y; acc.z += f1.x; acc.w += f1.y;
        }
    }

    if (act) {
        float d = g_dis[node];
        float o0, o1, o2, o3;
        if (MODE == 1) {
            float4 b = *(const float4*)&bias[lane * 4];
            o0 = d * fmaxf(fmaf(d, acc.x, b.x), 0.f);
            o1 = d * fmaxf(fmaf(d, acc.y, b.y), 0.f);
            o2 = d * fmaxf(fmaf(d, acc.z, b.z), 0.f);
            o3 = d * fmaxf(fmaf(d, acc.w, b.w), 0.f);
        } else {
            o0 = d * acc.x; o1 = d * acc.y; o2 = d * acc.z; o3 = d * acc.w;
        }
        __half2 h0 = __floats2half2_rn(o0, o1);
        __half2 h1 = __floats2half2_rn(o2, o3);
        uint2 u;
        u.x = *(const unsigned*)&h0;
        u.y = *(const unsigned*)&h1;
        ((uint2*)(outh + (size_t)node * H1))[lane] = u;
    }
}

// ================= launch =================
extern "C" void kernel_launch(void* const* d_in, const int* in_sizes, int n_in,
                              void* d_out, int out_size) {
    const float* x   = (const float*)d_in[0];
    const int*   ei  = (const int*)d_in[1];
    const float* W1  = (const float*)d_in[2];
    const float* b1  = (const float*)d_in[3];
    const float* W2  = (const float*)d_in[4];
    const float* b2  = (const float*)d_in[5];
    const float* Wfc = (const float*)d_in[6];
    const float* bfc = (const float*)d_in[7];
    float*       out = (float*)d_out;

    int nN = in_sizes[0] / FIN;
    int nE = in_sizes[1] / 2;
    const int* rowI = ei;
    const int* colI = ei + nE;

    __half *p_y1h, *p_y2h, *p_s2h;
    float  *p_xw2;
    int    *p_deg, *p_total;
    cudaGetSymbolAddress((void**)&p_y1h,  g_y1h);
    cudaGetSymbolAddress((void**)&p_y2h,  g_y2h);
    cudaGetSymbolAddress((void**)&p_s2h,  g_s2h);
    cudaGetSymbolAddress((void**)&p_xw2,  g_xw2);
    cudaGetSymbolAddress((void**)&p_deg,  g_deg);
    cudaGetSymbolAddress((void**)&p_total, g_total);

    // --- degree + CSR build ---
    cudaMemsetAsync(p_deg, 0, (size_t)nN * sizeof(int));
    cudaMemsetAsync(p_total, 0, sizeof(int));
    {
        int nQ = nE / 4 + 1;
        k_count_deg<<<(nQ + 255) / 256, 256>>>(colI, nE);
        k_assign   <<<(nN + 255) / 256, 256>>>(nN);
        k_fill     <<<(nQ + 255) / 256, 256>>>(rowI, colI, nE);
    }

    // --- weight converts ---
    k_conv_w1<<<(128 * 120 + 255) / 256, 256>>>(W1);
    k_conv_w2<<<(112 * 208 + 255) / 256, 256>>>(W2);

    // --- layer 1 (WMMA): y1h = fp16( d_r ⊙ (x @ W1) ) ---
    k_dense1_wmma<<<(nN + 63) / 64, 128>>>(x, p_y1h, nN);

    // --- agg1 + mid fused: y2h = fp16( d ⊙ relu(d ⊙ (y1_self + Σ y1[src]) + b1) ) ---
    k_gather_h<C4_H1, 1><<<(nN + 7) / 8, dim3(32, 8)>>>(
        p_y1h, b1, p_y2h, nN);

    // --- agg2 (commuted before GEMM): s2h = fp16( d ⊙ (y2_self + Σ y2[src]) ) ---
    k_gather_h<C4_H1, 2><<<(nN + 7) / 8, dim3(32, 8)>>>(
        p_y2h, nullptr, p_s2h, nN);

    // --- layer 2 (WMMA): xw2 = s2h @ W2 + b2 (fp32) ---
    k_dense2_wmma<<<(nN + 63) / 64, 128>>>(p_s2h, b2, p_xw2, nN);

    // --- FC: out = relu(xw2) @ Wfc + bfc ---
    k_dense<H2, FOUT, 8, 4, 1><<<(nN + 31) / 32, dim3(FOUT, 8)>>>(
        p_xw2, Wfc, bfc, out, nN);
}

// round 14
// speedup vs baseline: 3.5278x; 1.3006x over previous
#include <cuda_runtime.h>
#include <cuda_fp16.h>
#include <mma.h>
#include <cstddef>

using namespace nvcuda;

#define NN 50000
#define NE_MAX 800000
#define FIN 128
#define H1 100
#define H2 200
#define FOUT 16
#define C4_H1 (H1 / 4)   // 25 4-float chunks per row

// -------- scratch (static device globals; no allocation) --------
__device__ __align__(16) int    g_deg[NN];
__device__ __align__(16) float  g_dis[NN];
__device__ __align__(16) int    g_off[NN];
__device__ __align__(16) int    g_cur[NN];
__device__               int    g_total;
__device__ __align__(16) int    g_src[NE_MAX];
__device__ __align__(16) __half g_w1h[128 * 120];        // W1 fp16, N 100->120
__device__ __align__(16) __half g_w2h[112 * 208];        // W2 fp16, K 100->112, N 200->208
__device__ __align__(16) __half g_wfh[208 * FOUT];       // Wfc fp16, K 200->208
__device__ __align__(16) __half g_y1h[(size_t)NN * H1];  // fp16 gather payload 1
__device__ __align__(16) __half g_y2h[(size_t)NN * H1];  // fp16 gather payload 2
__device__ __align__(16) __half g_s2h[(size_t)NN * H1];  // fp16 dense2 input

// ================= degree / CSR build =================
__global__ void k_count_deg(const int* __restrict__ col, int nE) {
    int q = blockIdx.x * blockDim.x + threadIdx.x;
    int nQ = nE >> 2;
    if (q < nQ) {
        int4 c = *(const int4*)(col + q * 4);
        if ((unsigned)c.x < (unsigned)NN) atomicAdd(&g_deg[c.x], 1);
        if ((unsigned)c.y < (unsigned)NN) atomicAdd(&g_deg[c.y], 1);
        if ((unsigned)c.z < (unsigned)NN) atomicAdd(&g_deg[c.z], 1);
        if ((unsigned)c.w < (unsigned)NN) atomicAdd(&g_deg[c.w], 1);
    } else if (q == nQ) {
        for (int e = nQ * 4; e < nE; e++) {
            int t = col[e];
            if ((unsigned)t < (unsigned)NN) atomicAdd(&g_deg[t], 1);
        }
    }
}

__global__ void k_assign(int n) {
    int i = blockIdx.x * blockDim.x + threadIdx.x;
    if (i >= n) return;
    int d = g_deg[i];
    g_dis[i] = rsqrtf((float)(d + 1));
    int off = atomicAdd(&g_total, d);
    g_off[i] = off;
    g_cur[i] = off;
}

__global__ void k_fill(const int* __restrict__ row, const int* __restrict__ col, int nE) {
    int q = blockIdx.x * blockDim.x + threadIdx.x;
    int nQ = nE >> 2;
    if (q < nQ) {
        int4 r = *(const int4*)(row + q * 4);
        int4 c = *(const int4*)(col + q * 4);
        int s0 = -1, s1 = -1, s2 = -1, s3 = -1;
        if ((unsigned)c.x < (unsigned)NN && (unsigned)r.x < (unsigned)NN) s0 = atomicAdd(&g_cur[c.x], 1);
        if ((unsigned)c.y < (unsigned)NN && (unsigned)r.y < (unsigned)NN) s1 = atomicAdd(&g_cur[c.y], 1);
        if ((unsigned)c.z < (unsigned)NN && (unsigned)r.z < (unsigned)NN) s2 = atomicAdd(&g_cur[c.z], 1);
        if ((unsigned)c.w < (unsigned)NN && (unsigned)r.w < (unsigned)NN) s3 = atomicAdd(&g_cur[c.w], 1);
        if (s0 >= 0) g_src[s0] = r.x;
        if (s1 >= 0) g_src[s1] = r.y;
        if (s2 >= 0) g_src[s2] = r.z;
        if (s3 >= 0) g_src[s3] = r.w;
    } else if (q == nQ) {
        for (int e = nQ * 4; e < nE; e++) {
            int rr = row[e], t = col[e];
            if ((unsigned)rr >= (unsigned)NN || (unsigned)t >= (unsigned)NN) continue;
            int slot = atomicAdd(&g_cur[t], 1);
            g_src[slot] = rr;
        }
    }
}

// ================= single fused weight convert =================
#define W1_ELEMS (128 * 120)
#define W2_ELEMS (112 * 208)
#define WF_ELEMS (208 * FOUT)
__global__ void k_conv_w(const float* __restrict__ W1, const float* __restrict__ W2,
                         const float* __restrict__ Wfc) {
    int idx = blockIdx.x * blockDim.x + threadIdx.x;
    if (idx < W1_ELEMS) {
        int k = idx / 120, j = idx - k * 120;
        g_w1h[idx] = __float2half((j < H1) ? W1[(size_t)k * H1 + j] : 0.f);
    } else if (idx < W1_ELEMS + W2_ELEMS) {
        int t = idx - W1_ELEMS;
        int k = t / 208, j = t - k * 208;
        g_w2h[t] = __float2half((k < H1 && j < H2) ? W2[(size_t)k * H2 + j] : 0.f);
    } else if (idx < W1_ELEMS + W2_ELEMS + WF_ELEMS) {
        int t = idx - W1_ELEMS - W2_ELEMS;
        int k = t / FOUT, j = t - k * FOUT;
        g_wfh[t] = __float2half((k < H2) ? Wfc[(size_t)k * FOUT + j] : 0.f);
    }
}

// ================= dense1 via WMMA (fp16 in, fp32 acc, fp16 out scaled by dis) =================
__global__ void __launch_bounds__(128)
k_dense1_wmma(const float* __restrict__ x, __half* __restrict__ y1h, int nRows) {
    __shared__ __align__(16) __half s_x[64 * 128];   // 16 KB
    __shared__ __align__(16) __half s_w[128 * 120];  // 30 KB

    int tid  = threadIdx.x;
    int warp = tid >> 5;
    int lane = tid & 31;
    int r0   = blockIdx.x * 64;

    const float4* x4 = (const float4*)x;
    for (int i = tid; i < 64 * 32; i += 128) {
        int r = i >> 5, c = i & 31;
        int gr = r0 + r;
        float4 v = (gr < nRows) ? x4[(size_t)gr * 32 + c] : make_float4(0.f, 0.f, 0.f, 0.f);
        __half2 h0 = __floats2half2_rn(v.x, v.y);
        __half2 h1 = __floats2half2_rn(v.z, v.w);
        uint2 u = make_uint2(*(unsigned*)&h0, *(unsigned*)&h1);
        *(uint2*)&s_x[r * 128 + c * 4] = u;
    }
    {
        const int4* wsrc = (const int4*)g_w1h;
        int4* wdst = (int4*)s_w;
        for (int i = tid; i < 1920; i += 128) wdst[i] = wsrc[i];
    }
    __syncthreads();

    wmma::fragment<wmma::matrix_a, 16, 16, 16, __half, wmma::row_major> afrag[8];
#pragma unroll
    for (int k = 0; k < 8; k++)
        wmma::load_matrix_sync(afrag[k], &s_x[(warp * 16) * 128 + k * 16], 128);
    __syncthreads();

    float* s_c = (float*)s_x + warp * 256;

    for (int n = 0; n < 7; n++) {
        wmma::fragment<wmma::accumulator, 16, 16, 16, float> acc;
        wmma::fill_fragment(acc, 0.f);
#pragma unroll
        for (int k = 0; k < 8; k++) {
            wmma::fragment<wmma::matrix_b, 16, 16, 16, __half, wmma::row_major> bfrag;
            wmma::load_matrix_sync(bfrag, &s_w[(k * 16) * 120 + n * 16], 120);
            wmma::mma_sync(acc, afrag[k], bfrag, acc);
        }
        wmma::store_matrix_sync(s_c, acc, 16, wmma::mem_row_major);
        __syncwarp();
        for (int i = lane; i < 128; i += 32) {
            int r = i >> 3, p = i & 7;
            int gr = r0 + warp * 16 + r;
            int gc = n * 16 + p * 2;
            if (gr < nRows && gc < H1) {
                float d = g_dis[gr];
                __half2 h = __floats2half2_rn(s_c[r * 16 + p * 2] * d,
                                              s_c[r * 16 + p * 2 + 1] * d);
                *(unsigned*)&y1h[(size_t)gr * H1 + gc] = *(unsigned*)&h;
            }
        }
        __syncwarp();
    }
}

// ================= dense2 + FC fused via WMMA =================
// stage 1: mid[64][208](fp16, smem) = relu( s2h @ W2 + b2 )   (pad cols zeroed)
// stage 2: out[64][16](fp32)        = mid @ Wfc + bfc
__global__ void __launch_bounds__(128)
k_dense2_fc_wmma(const __half* __restrict__ s2h, const float* __restrict__ b2,
                 const float* __restrict__ bfc, float* __restrict__ out, int nRows) {
    __shared__ __align__(16) __half s_a[64 * 112];    // 14 KB
    __shared__ __align__(16) __half s_r[64 * 208];    // 26 KB (relu mid, fp16)
    __shared__ __align__(16) float  s_c4[4 * 256];    // 4 KB epilogue scratch

    int tid  = threadIdx.x;
    int warp = tid >> 5;
    int lane = tid & 31;
    int r0   = blockIdx.x * 64;

    // load s2h tile: 25 real uint2 chunks per row, pad cols 100..111 zero
    for (int i = tid; i < 64 * 28; i += 128) {
        int r = i / 28, c = i - r * 28;
        int gr = r0 + r;
        uint2 u = make_uint2(0u, 0u);
        if (gr < nRows && c < 25)
            u = __ldg((const uint2*)(s2h + (size_t)gr * H1) + c);
        *(uint2*)&s_a[r * 112 + c * 4] = u;
    }
    __syncthreads();

    wmma::fragment<wmma::matrix_a, 16, 16, 16, __half, wmma::row_major> afrag[7];
#pragma unroll
    for (int k = 0; k < 7; k++)
        wmma::load_matrix_sync(afrag[k], &s_a[(warp * 16) * 112 + k * 16], 112);

    float* s_c = s_c4 + warp * 256;

    // ---- stage 1: 13 n-tiles of relu(s2h@W2+b2) -> s_r (fp16) ----
    for (int n = 0; n < 13; n++) {
        wmma::fragment<wmma::accumulator, 16, 16, 16, float> acc;
        wmma::fill_fragment(acc, 0.f);
#pragma unroll
        for (int k = 0; k < 7; k++) {
            wmma::fragment<wmma::matrix_b, 16, 16, 16, __half, wmma::row_major> bfrag;
            wmma::load_matrix_sync(bfrag, &g_w2h[(k * 16) * 208 + n * 16], 208);
            wmma::mma_sync(acc, afrag[k], bfrag, acc);
        }
        wmma::store_matrix_sync(s_c, acc, 16, wmma::mem_row_major);
        __syncwarp();
        for (int i = lane; i < 128; i += 32) {   // 16 rows x 8 pairs
            int r = i >> 3, p = i & 7;
            int gc = n * 16 + p * 2;
            float v0 = 0.f, v1 = 0.f;
            if (gc < H2) {     // H2 is even; pair fully in-range or fully out
                v0 = fmaxf(s_c[r * 16 + p * 2]     + __ldg(&b2[gc]),     0.f);
                v1 = fmaxf(s_c[r * 16 + p * 2 + 1] + __ldg(&b2[gc + 1]), 0.f);
            }
            __half2 h = __floats2half2_rn(v0, v1);
            *(unsigned*)&s_r[(warp * 16 + r) * 208 + gc] = *(unsigned*)&h;
        }
        __syncwarp();
    }
    __syncthreads();

    // ---- stage 2: out = s_r @ Wfc + bfc  (one 16-wide N tile) ----
    {
        wmma::fragment<wmma::accumulator, 16, 16, 16, float> acc;
        wmma::fill_fragment(acc, 0.f);
#pragma unroll
        for (int k = 0; k < 13; k++) {
            wmma::fragment<wmma::matrix_a, 16, 16, 16, __half, wmma::row_major> a2;
            wmma::load_matrix_sync(a2, &s_r[(warp * 16) * 208 + k * 16], 208);
            wmma::fragment<wmma::matrix_b, 16, 16, 16, __half, wmma::row_major> bfrag;
            wmma::load_matrix_sync(bfrag, &g_wfh[(k * 16) * FOUT], FOUT);
            wmma::mma_sync(acc, a2, bfrag, acc);
        }
        wmma::store_matrix_sync(s_c, acc, 16, wmma::mem_row_major);
        __syncwarp();
        for (int i = lane; i < 256; i += 32) {   // 16 rows x 16 cols
            int r = i >> 4, c = i & 15;
            int gr = r0 + warp * 16 + r;
            if (gr < nRows)
                out[(size_t)gr * FOUT + c] = s_c[r * 16 + c] + __ldg(&bfc[c]);
        }
    }
}

// ================= CSR gather aggregation, fp16 payload =================
// MODE 1: out(fp16) = d * relu(d * acc + bias)
// MODE 2: out(fp16) = d * acc
template <int C4, int MODE>
__global__ void __launch_bounds__(256)
k_gather_h(const __half* __restrict__ y, const float* __restrict__ bias,
           __half* __restrict__ outh, int nN) {
    int node = blockIdx.x * blockDim.y + threadIdx.y;
    if (node >= nN) return;
    int lane  = threadIdx.x;
    int start = g_off[node];
    int cnt   = g_deg[node];
    bool act  = (lane < C4);

    float4 acc = make_float4(0.f, 0.f, 0.f, 0.f);
    if (act) {
        uint2 u = __ldg((const uint2*)(y + (size_t)node * H1) + lane);
        float2 f0 = __half22float2(*(const __half2*)&u.x);
        float2 f1 = __half22float2(*(const __half2*)&u.y);
        acc = make_float4(f0.x, f0.y, f1.x, f1.y);
    }

    int j = 0;
    for (; j + 8 <= cnt; j += 8) {
        int rr[8];
#pragma unroll
        for (int u = 0; u < 8; u++) rr[u] = __ldg(&g_src[start + j + u]);
#pragma unroll
        for (int u = 0; u < 8; u++) {
            if (act) {
                uint2 w = __ldg((const uint2*)(y + (size_t)rr[u] * H1) + lane);
                float2 f0 = __half22float2(*(const __half2*)&w.x);
                float2 f1 = __half22float2(*(const __half2*)&w.y);
                acc.x += f0.x; acc.y += f0.y; acc.z += f1.x; acc.w += f1.y;
            }
        }
    }
    if (j + 4 <= cnt) {
        int rr[4];
#pragma unroll
        for (int u = 0; u < 4; u++) rr[u] = __ldg(&g_src[start + j + u]);
#pragma unroll
        for (int u = 0; u < 4; u++) {
            if (act) {
                uint2 w = __ldg((const uint2*)(y + (size_t)rr[u] * H1) + lane);
                float2 f0 = __half22float2(*(const __half2*)&w.x);
                float2 f1 = __half22float2(*(const __half2*)&w.y);
                acc.x += f0.x; acc.y += f0.y; acc.z += f1.x; acc.w += f1.y;
            }
        }
        j += 4;
    }
    for (; j < cnt; j++) {
        int r = __ldg(&g_src[start + j]);
        if (act) {
            uint2 w = __ldg((const uint2*)(y + (size_t)r * H1) + lane);
            float2 f0 = __half22float2(*(const __half2*)&w.x);
            float2 f1 = __half22float2(*(const __half2*)&w.y);
            acc.x += f0.x; acc.y += f0.y; acc.z += f1.x; acc.w += f1.y;
        }
    }

    if (act) {
        float d = g_dis[node];
        float o0, o1, o2, o3;
        if (MODE == 1) {
            float4 b = *(const float4*)&bias[lane * 4];
            o0 = d * fmaxf(fmaf(d, acc.x, b.x), 0.f);
            o1 = d * fmaxf(fmaf(d, acc.y, b.y), 0.f);
            o2 = d * fmaxf(fmaf(d, acc.z, b.z), 0.f);
            o3 = d * fmaxf(fmaf(d, acc.w, b.w), 0.f);
        } else {
            o0 = d * acc.x; o1 = d * acc.y; o2 = d * acc.z; o3 = d * acc.w;
        }
        __half2 h0 = __floats2half2_rn(o0, o1);
        __half2 h1 = __floats2half2_rn(o2, o3);
        uint2 u;
        u.x = *(const unsigned*)&h0;
        u.y = *(const unsigned*)&h1;
        ((uint2*)(outh + (size_t)node * H1))[lane] = u;
    }
}

// ================= launch =================
extern "C" void kernel_launch(void* const* d_in, const int* in_sizes, int n_in,
                              void* d_out, int out_size) {
    const float* x   = (const float*)d_in[0];
    const int*   ei  = (const int*)d_in[1];
    const float* W1  = (const float*)d_in[2];
    const float* b1  = (const float*)d_in[3];
    const float* W2  = (const float*)d_in[4];
    const float* b2  = (const float*)d_in[5];
    const float* Wfc = (const float*)d_in[6];
    const float* bfc = (const float*)d_in[7];
    float*       out = (float*)d_out;

    int nN = in_sizes[0] / FIN;
    int nE = in_sizes[1] / 2;
    const int* rowI = ei;
    const int* colI = ei + nE;

    __half *p_y1h, *p_y2h, *p_s2h;
    int    *p_deg, *p_total;
    cudaGetSymbolAddress((void**)&p_y1h,  g_y1h);
    cudaGetSymbolAddress((void**)&p_y2h,  g_y2h);
    cudaGetSymbolAddress((void**)&p_s2h,  g_s2h);
    cudaGetSymbolAddress((void**)&p_deg,  g_deg);
    cudaGetSymbolAddress((void**)&p_total, g_total);

    // --- degree + CSR build ---
    cudaMemsetAsync(p_deg, 0, (size_t)nN * sizeof(int));
    cudaMemsetAsync(p_total, 0, sizeof(int));
    {
        int nQ = nE / 4 + 1;
        k_count_deg<<<(nQ + 255) / 256, 256>>>(colI, nE);
        k_assign   <<<(nN + 255) / 256, 256>>>(nN);
        k_fill     <<<(nQ + 255) / 256, 256>>>(rowI, colI, nE);
    }

    // --- fused weight converts ---
    k_conv_w<<<(W1_ELEMS + W2_ELEMS + WF_ELEMS + 255) / 256, 256>>>(W1, W2, Wfc);

    // --- layer 1 (WMMA): y1h = fp16( d_r ⊙ (x @ W1) ) ---
    k_dense1_wmma<<<(nN + 63) / 64, 128>>>(x, p_y1h, nN);

    // --- agg1 + mid fused: y2h = fp16( d ⊙ relu(d ⊙ (y1_self + Σ y1[src]) + b1) ) ---
    k_gather_h<C4_H1, 1><<<(nN + 7) / 8, dim3(32, 8)>>>(
        p_y1h, b1, p_y2h, nN);

    // --- agg2 (commuted before GEMM): s2h = fp16( d ⊙ (y2_self + Σ y2[src]) ) ---
    k_gather_h<C4_H1, 2><<<(nN + 7) / 8, dim3(32, 8)>>>(
        p_y2h, nullptr, p_s2h, nN);

    // --- layer 2 + FC fused (WMMA): out = relu(s2h @ W2 + b2) @ Wfc + bfc ---
    k_dense2_fc_wmma<<<(nN + 63) / 64, 128>>>(p_s2h, b2, bfc, out, nN);
}